// round 3
// baseline (speedup 1.0000x reference)
#include <cuda_runtime.h>
#include <cstdint>

#define N_NODES 16384
#define N_EDGES 131072
#define F_IN 6
#define S_DIM 4
#define G_NUM 256
#define HH 30
#define C1 32
#define C2 64
#define C3 32

typedef unsigned long long ull;

// ---------------- scratch (no cudaMalloc allowed) ----------------
__device__ float g_B1[N_NODES * C1];   // ECC1 agg -> x1 (pre-relu)
__device__ float g_B2[N_NODES * C2];   // ECC2 agg -> x2 (pre-relu)
__device__ float g_XW[N_NODES * C3];   // relu(x2) @ gcn_W
__device__ float g_B3[N_NODES * C3];   // GCN agg

// packed f32x2 FMA (Blackwell)
__device__ __forceinline__ void ffma2(ull &acc, ull a, ull b) {
    asm("fma.rn.f32x2 %0, %1, %2, %0;" : "+l"(acc) : "l"(a), "l"(b));
}

// vector reduction (sm_90+): 4x fewer atomic ops than scalar atomicAdd
__device__ __forceinline__ void red4(float* p, float a, float b, float c, float d) {
    asm volatile("red.global.add.v4.f32 [%0], {%1, %2, %3, %4};"
                 :: "l"(p), "f"(a), "f"(b), "f"(c), "f"(d) : "memory");
}

// ---------------- ECC edge kernel: fused MLP + P@B GEMM + scatter ----------------
// msg[e,c] = sum_{h,f} h2[e,h]*xs[e,f]*wk[h*F+f, c] + sum_f xs[e,f]*bk[f, c]
//          = (P @ B)[e,c]   with  P[e, h*F+f] = h2*xs,  B = wk rows + F bias rows.
template <int F, int C>
struct EccSmem {
    static constexpr int TM = 128;
    static constexpr int KC = 32;
    float w0[S_DIM * HH];
    float b0v[HH];
    float b1v[HH];
    float w1[HH * HH];
    float ef[TM * S_DIM];
    int   srcs[TM];
    int   tgts[TM];
    float h2[TM * HH];
    float xs[TM * F];
    __align__(16) ull A[TM * KC];        // duplicated {a,a}; also h1 staging (TM*HH floats fit)
    __align__(16) ull B[KC * (C / 2)];   // B rows as f32x2 pairs
};

template <int F, int C, bool RELU_IN>
__global__ __launch_bounds__(256, 2) void ecc_edge_kernel(
    const float* __restrict__ xin, const float* __restrict__ efeat,
    const int* __restrict__ src, const int* __restrict__ tgt,
    const float* __restrict__ w0, const float* __restrict__ b0,
    const float* __restrict__ w1, const float* __restrict__ b1,
    const float* __restrict__ wk, const float* __restrict__ bk,
    float* __restrict__ agg)
{
    constexpr int TM = 128, KC = 32, NT = 256;
    constexpr int K_MAIN = HH * F;
    constexpr int K_TOT  = K_MAIN + F;
    constexpr int NSLAB  = (K_TOT + KC - 1) / KC;
    constexpr int UC = (C == 64) ? 4 : 2;      // ull cols per thread
    constexpr int GC = (C / 2) / UC;           // col groups = 8
    constexpr int RM = TM / (NT / GC);         // rows per thread = 4

    extern __shared__ __align__(16) char smraw[];
    EccSmem<F, C>& S = *reinterpret_cast<EccSmem<F, C>*>(smraw);
    float* h1 = reinterpret_cast<float*>(S.A);   // overlay: h1 dead before A is built

    const int tid = threadIdx.x;
    const int i0  = blockIdx.x * TM;

    // --- stage 0: weights + edge tile + indices ---
    for (int j = tid; j < S_DIM * HH; j += NT) S.w0[j] = w0[j];
    for (int j = tid; j < HH; j += NT) { S.b0v[j] = b0[j]; S.b1v[j] = b1[j]; }
    for (int j = tid; j < HH * HH; j += NT) S.w1[j] = w1[j];
    for (int j = tid; j < TM * S_DIM; j += NT) S.ef[j] = efeat[(size_t)i0 * S_DIM + j];
    for (int j = tid; j < TM; j += NT) { S.srcs[j] = src[i0 + j]; S.tgts[j] = tgt[i0 + j]; }
    __syncthreads();

    // --- gather x[src] tile (relu fused when input is a pre-activation buffer) ---
    if constexpr (F % 4 == 0) {
        for (int j = tid; j < TM * (F / 4); j += NT) {
            int i = j / (F / 4), q = j - i * (F / 4);
            float4 v = __ldg(reinterpret_cast<const float4*>(xin + (size_t)S.srcs[i] * F) + q);
            if (RELU_IN) { v.x = fmaxf(v.x, 0.f); v.y = fmaxf(v.y, 0.f);
                           v.z = fmaxf(v.z, 0.f); v.w = fmaxf(v.w, 0.f); }
            reinterpret_cast<float4*>(S.xs)[j] = v;
        }
    } else {
        for (int j = tid; j < TM * F; j += NT) {
            int i = j / F, f = j - i * F;
            float v = __ldg(xin + (size_t)S.srcs[i] * F + f);
            S.xs[j] = RELU_IN ? fmaxf(v, 0.f) : v;
        }
    }
    // --- edge MLP ---
    for (int j = tid; j < TM * HH; j += NT) {
        int i = j / HH, jj = j - i * HH;
        float a = S.b0v[jj];
        #pragma unroll
        for (int s = 0; s < S_DIM; s++) a += S.ef[i * S_DIM + s] * S.w0[s * HH + jj];
        h1[j] = fmaxf(a, 0.f);
    }
    __syncthreads();
    for (int j = tid; j < TM * HH; j += NT) {
        int i = j / HH, jj = j - i * HH;
        float a = S.b1v[jj];
        #pragma unroll
        for (int h = 0; h < HH; h++) a += h1[i * HH + h] * S.w1[h * HH + jj];
        S.h2[j] = fmaxf(a, 0.f);
    }

    // --- GEMM MSG[TM,C] = P @ B ---
    const int cg   = tid % GC;
    const int row0 = (tid / GC) * RM;
    const int cp0  = cg * UC;

    ull acc[RM][UC];
    #pragma unroll
    for (int r = 0; r < RM; r++)
        #pragma unroll
        for (int u = 0; u < UC; u++) acc[r][u] = 0ull;

    for (int slab = 0; slab < NSLAB; slab++) {
        const int k0 = slab * KC;
        __syncthreads();   // protects A (h1 at slab 0) and B from readers

        // build A slab: A[i][kk] = {a,a}
        #pragma unroll
        for (int t = 0; t < (TM * KC) / NT; t++) {
            int j = tid + t * NT;
            int i = j >> 5, kk = j & 31;
            int k = k0 + kk;
            float a = 0.f;
            if (k < K_MAIN)       a = S.h2[i * HH + k / F] * S.xs[i * F + k % F];
            else if (k < K_TOT)   a = S.xs[i * F + (k - K_MAIN)];
            unsigned u = __float_as_uint(a);
            S.A[j] = ((ull)u << 32) | u;
        }
        // build B slab
        #pragma unroll
        for (int t = 0; t < (KC * (C / 2)) / NT; t++) {
            int j = tid + t * NT;
            int kk = j / (C / 2), cp = j - kk * (C / 2);
            int k = k0 + kk;
            float2 bv = make_float2(0.f, 0.f);
            if (k < K_MAIN)      bv = __ldg(reinterpret_cast<const float2*>(wk) + (size_t)k * (C / 2) + cp);
            else if (k < K_TOT)  bv = __ldg(reinterpret_cast<const float2*>(bk) + (size_t)(k - K_MAIN) * (C / 2) + cp);
            S.B[j] = ((ull)__float_as_uint(bv.y) << 32) | (ull)__float_as_uint(bv.x);
        }
        __syncthreads();

        #pragma unroll
        for (int kk = 0; kk < KC; kk += 2) {
            ull b0r[UC], b1r[UC];
            #pragma unroll
            for (int u = 0; u < UC; u += 2) {
                ulonglong2 t0 = *reinterpret_cast<const ulonglong2*>(&S.B[kk * (C / 2) + cp0 + u]);
                b0r[u] = t0.x; b0r[u + 1] = t0.y;
                ulonglong2 t1 = *reinterpret_cast<const ulonglong2*>(&S.B[(kk + 1) * (C / 2) + cp0 + u]);
                b1r[u] = t1.x; b1r[u + 1] = t1.y;
            }
            #pragma unroll
            for (int r = 0; r < RM; r++) {
                ulonglong2 av = *reinterpret_cast<const ulonglong2*>(&S.A[(row0 + r) * KC + kk]);
                #pragma unroll
                for (int u = 0; u < UC; u++) {
                    ffma2(acc[r][u], av.x, b0r[u]);
                    ffma2(acc[r][u], av.y, b1r[u]);
                }
            }
        }
    }

    // --- scatter-add (vector red) ---
    #pragma unroll
    for (int r = 0; r < RM; r++) {
        int i = row0 + r;
        float* dst = agg + (size_t)S.tgts[i] * C + 2 * cp0;
        #pragma unroll
        for (int u = 0; u < UC; u += 2) {
            float2 v0 = *reinterpret_cast<float2*>(&acc[r][u]);
            float2 v1 = *reinterpret_cast<float2*>(&acc[r][u + 1]);
            red4(dst + 2 * u, v0.x, v0.y, v1.x, v1.y);
        }
    }
}

// ---------------- node GEMM: out[n,c] = [bias[c]] + relu?(x[n,:]) @ root[:,c] ----------------
template <int F, int C, bool BIAS, bool RELU_IN>
__global__ __launch_bounds__(256) void base2_kernel(
    const float* __restrict__ x, const float* __restrict__ root,
    const float* __restrict__ bias, float* __restrict__ out)
{
    __shared__ float sroot[F * C];
    __shared__ float sb[C];
    const int tid = threadIdx.x;
    for (int j = tid; j < F * C; j += 256) sroot[j] = root[j];
    if (BIAS) for (int j = tid; j < C; j += 256) sb[j] = bias[j];
    __syncthreads();

    constexpr int QC = C / 4;
    int idx = blockIdx.x * 256 + tid;
    int n = idx / QC, q = (idx - n * QC) * 4;
    if (n >= N_NODES) return;

    float4 a = BIAS ? make_float4(sb[q], sb[q + 1], sb[q + 2], sb[q + 3])
                    : make_float4(0.f, 0.f, 0.f, 0.f);
    const float* xr = x + (size_t)n * F;
    #pragma unroll
    for (int f = 0; f < F; f++) {
        float xv = __ldg(xr + f);
        if (RELU_IN) xv = fmaxf(xv, 0.f);
        float4 rv = *reinterpret_cast<const float4*>(&sroot[f * C + q]);
        a.x += xv * rv.x; a.y += xv * rv.y; a.z += xv * rv.z; a.w += xv * rv.w;
    }
    *reinterpret_cast<float4*>(out + (size_t)n * C + q) = a;
}

__global__ void zero_kernel(float* __restrict__ buf, int n)
{
    int i = blockIdx.x * blockDim.x + threadIdx.x;
    if (i < n) buf[i] = 0.f;
}

// GCN weighted SpMM: b3[tgt, :] += w * xw[src, :]   (8 lanes/edge, float4 red)
__global__ void gcn_edge_kernel(const float* __restrict__ xw,
                                const int* __restrict__ gs, const int* __restrict__ gt,
                                const float* __restrict__ gw, float* __restrict__ b3)
{
    int idx = blockIdx.x * blockDim.x + threadIdx.x;
    int m = idx >> 3, q = (idx & 7) * 4;
    if (m >= N_EDGES + N_NODES) return;
    float w = __ldg(gw + m);
    float4 v = __ldg(reinterpret_cast<const float4*>(xw + (size_t)__ldg(gs + m) * C3 + q));
    red4(b3 + (size_t)__ldg(gt + m) * C3 + q, w * v.x, w * v.y, w * v.z, w * v.w);
}

// x3 = relu(b3 + gcn_b); out[seg[n], :] += x3[n, :]
__global__ void pool_kernel(const float* __restrict__ b3, const float* __restrict__ gb,
                            const int* __restrict__ seg, float* __restrict__ out)
{
    int idx = blockIdx.x * blockDim.x + threadIdx.x;
    int n = idx >> 3, q = (idx & 7) * 4;
    if (n >= N_NODES) return;
    float4 v = *reinterpret_cast<const float4*>(b3 + (size_t)n * C3 + q);
    float a = fmaxf(v.x + __ldg(gb + q), 0.f);
    float b = fmaxf(v.y + __ldg(gb + q + 1), 0.f);
    float c = fmaxf(v.z + __ldg(gb + q + 2), 0.f);
    float d = fmaxf(v.w + __ldg(gb + q + 3), 0.f);
    red4(out + (size_t)__ldg(seg + n) * C3 + q, a, b, c, d);
}

// ---------------- launch ----------------
extern "C" void kernel_launch(void* const* d_in, const int* in_sizes, int n_in,
                              void* d_out, int out_size)
{
    (void)in_sizes; (void)n_in; (void)out_size;
    const float* x     = (const float*)d_in[0];
    const float* e     = (const float*)d_in[1];
    const int*   src   = (const int*)d_in[2];
    const int*   tgt   = (const int*)d_in[3];
    const int*   seg   = (const int*)d_in[4];
    const int*   gsrc  = (const int*)d_in[5];
    const int*   gtgt  = (const int*)d_in[6];
    const float* gw    = (const float*)d_in[7];
    const float* e1_w0 = (const float*)d_in[8];
    const float* e1_b0 = (const float*)d_in[9];
    const float* e1_w1 = (const float*)d_in[10];
    const float* e1_b1 = (const float*)d_in[11];
    const float* e1_wk = (const float*)d_in[12];
    const float* e1_bk = (const float*)d_in[13];
    const float* e1_root = (const float*)d_in[14];
    const float* e1_bias = (const float*)d_in[15];
    const float* e2_w0 = (const float*)d_in[16];
    const float* e2_b0 = (const float*)d_in[17];
    const float* e2_w1 = (const float*)d_in[18];
    const float* e2_b1 = (const float*)d_in[19];
    const float* e2_wk = (const float*)d_in[20];
    const float* e2_bk = (const float*)d_in[21];
    const float* e2_root = (const float*)d_in[22];
    const float* e2_bias = (const float*)d_in[23];
    const float* gcn_W = (const float*)d_in[24];
    const float* gcn_b = (const float*)d_in[25];
    float* out = (float*)d_out;

    float *B1, *B2, *XW, *B3;
    cudaGetSymbolAddress((void**)&B1, g_B1);
    cudaGetSymbolAddress((void**)&B2, g_B2);
    cudaGetSymbolAddress((void**)&XW, g_XW);
    cudaGetSymbolAddress((void**)&B3, g_B3);

    const int smem1 = (int)sizeof(EccSmem<F_IN, C1>);
    const int smem2 = (int)sizeof(EccSmem<C1, C2>);
    cudaFuncSetAttribute((const void*)ecc_edge_kernel<F_IN, C1, false>,
                         cudaFuncAttributeMaxDynamicSharedMemorySize, smem1);
    cudaFuncSetAttribute((const void*)ecc_edge_kernel<C1, C2, true>,
                         cudaFuncAttributeMaxDynamicSharedMemorySize, smem2);

    // ECC layer 1: B1 = x@root1 + bias1 (+ messages); relu deferred to readers
    base2_kernel<F_IN, C1, true, false><<<(N_NODES * (C1 / 4) + 255) / 256, 256>>>(x, e1_root, e1_bias, B1);
    ecc_edge_kernel<F_IN, C1, false><<<N_EDGES / 128, 256, smem1>>>(
        x, e, src, tgt, e1_w0, e1_b0, e1_w1, e1_b1, e1_wk, e1_bk, B1);

    // ECC layer 2 (readers apply relu to B1)
    base2_kernel<C1, C2, true, true><<<(N_NODES * (C2 / 4) + 255) / 256, 256>>>(B1, e2_root, e2_bias, B2);
    ecc_edge_kernel<C1, C2, true><<<N_EDGES / 128, 256, smem2>>>(
        B1, e, src, tgt, e2_w0, e2_b0, e2_w1, e2_b1, e2_wk, e2_bk, B2);

    // GCN: xw = relu(B2) @ W ; B3 = scatter(gcn_w * xw[gcn_src] -> gcn_tgt)
    base2_kernel<C2, C3, false, true><<<(N_NODES * (C3 / 4) + 255) / 256, 256>>>(B2, gcn_W, nullptr, XW);
    zero_kernel<<<(N_NODES * C3 + 255) / 256, 256>>>(B3, N_NODES * C3);
    gcn_edge_kernel<<<((N_EDGES + N_NODES) * 8 + 255) / 256, 256>>>(XW, gsrc, gtgt, gw, B3);

    // relu(+bias) and global sum pool
    zero_kernel<<<(G_NUM * C3 + 255) / 256, 256>>>(out, G_NUM * C3);
    pool_kernel<<<(N_NODES * 8 + 255) / 256, 256>>>(B3, gcn_b, seg, out);
}

// round 8
// speedup vs baseline: 1.8286x; 1.8286x over previous
#include <cuda_runtime.h>
#include <cuda_bf16.h>
#include <cstdint>

#define N_NODES 16384
#define N_EDGES 131072
#define F_IN 6
#define S_DIM 4
#define G_NUM 256
#define HH 30
#define C1 32
#define C2 64
#define C3 32

#define K1MAIN (HH * F_IN)      // 180
#define K1TOT  (K1MAIN + F_IN)  // 186
#define K1PAD  192              // 12 k-chunks of 16
#define K2MAIN (HH * C1)        // 960
#define K2TOT  (K2MAIN + C1)    // 992
#define K2PAD  992              // 62 k-chunks of 16

// ---------------- scratch (no cudaMalloc allowed) ----------------
__device__ float g_B1[N_NODES * C1];
__device__ float g_B2[N_NODES * C2];
__device__ float g_XW[N_NODES * C3];
__device__ float g_B3[N_NODES * C3];
__device__ __nv_bfloat16 g_WT1_hi[C1 * K1PAD];
__device__ __nv_bfloat16 g_WT1_lo[C1 * K1PAD];
__device__ __nv_bfloat16 g_WT2_hi[C2 * K2PAD];
__device__ __nv_bfloat16 g_WT2_lo[C2 * K2PAD];

// ---------------- helpers ----------------
__device__ __forceinline__ void red4(float* p, float a, float b, float c, float d) {
    asm volatile("red.global.add.v4.f32 [%0], {%1, %2, %3, %4};"
                 :: "l"(p), "f"(a), "f"(b), "f"(c), "f"(d) : "memory");
}
__device__ __forceinline__ void red2(float* p, float a, float b) {
    asm volatile("red.global.add.v2.f32 [%0], {%1, %2};"
                 :: "l"(p), "f"(a), "f"(b) : "memory");
}

// pack (pA -> low half, pB -> high half) as bf16x2 hi, and residual lo
__device__ __forceinline__ void splitpair(uint32_t& h, uint32_t& l, float pA, float pB) {
    asm("cvt.rn.bf16x2.f32 %0, %1, %2;" : "=r"(h) : "f"(pB), "f"(pA));
    float rA = pA - __uint_as_float(h << 16);
    float rB = pB - __uint_as_float(h & 0xffff0000u);
    asm("cvt.rn.bf16x2.f32 %0, %1, %2;" : "=r"(l) : "f"(rB), "f"(rA));
}

__device__ __forceinline__ void mma_bf16(float* c, const uint32_t* a, uint32_t b0, uint32_t b1) {
    asm volatile("mma.sync.aligned.m16n8k16.row.col.f32.bf16.bf16.f32 "
                 "{%0,%1,%2,%3}, {%4,%5,%6,%7}, {%8,%9}, {%0,%1,%2,%3};"
                 : "+f"(c[0]), "+f"(c[1]), "+f"(c[2]), "+f"(c[3])
                 : "r"(a[0]), "r"(a[1]), "r"(a[2]), "r"(a[3]), "r"(b0), "r"(b1));
}

// ---------------- weight pre-transpose + bf16 hi/lo split ----------------
template <int C, int KMAIN, int KTOT, int KPAD>
__global__ void prep_wt_kernel(const float* __restrict__ wk, const float* __restrict__ bk,
                               __nv_bfloat16* __restrict__ hi, __nv_bfloat16* __restrict__ lo)
{
    int idx = blockIdx.x * 256 + threadIdx.x;
    if (idx >= C * KPAD) return;
    int c = idx / KPAD, k = idx - c * KPAD;
    float v = 0.f;
    if (k < KMAIN)      v = __ldg(wk + (size_t)k * C + c);
    else if (k < KTOT)  v = __ldg(bk + (size_t)(k - KMAIN) * C + c);
    __nv_bfloat16 h = __float2bfloat16(v);
    hi[idx] = h;
    lo[idx] = __float2bfloat16(v - __bfloat162float(h));
}

// ---------------- ECC layer: fused edge-MLP + bf16 3-MMA GEMM + scatter ----------------
// msg[e,c] = sum_k P[e,k]*WT[c,k],  P[e, h*F+f] = h2[e,h]*xs[e,f], + F identity rows for bk.
template <int F, int C, int KPAD, bool RELU_IN>
__global__ __launch_bounds__(256) void ecc_mma_kernel(
    const float* __restrict__ xin, const float* __restrict__ efeat,
    const int* __restrict__ src, const int* __restrict__ tgt,
    const float* __restrict__ w0, const float* __restrict__ b0,
    const float* __restrict__ w1, const float* __restrict__ b1,
    const __nv_bfloat16* __restrict__ wtHi, const __nv_bfloat16* __restrict__ wtLo,
    float* __restrict__ agg)
{
    constexpr int NT = 256, TM = 128;
    constexpr int XSTR = (F == 32) ? 36 : 8;      // padded row stride (bank-conflict-free)
    constexpr int NKC = KPAD / 16;
    constexpr int NNT = C / 8;                    // n8 tiles per warp (warp covers all C)
    constexpr int KMAIN = HH * F;
    constexpr int KTOT = KMAIN + F;

    __shared__ float S_w0[S_DIM * HH], S_b0v[HH], S_b1v[HH], S_w1[HH * HH];
    __shared__ float S_ef[TM * S_DIM];
    __shared__ int S_src[TM], S_tgt[TM];
    __shared__ float S_h2[TM * HH];
    constexpr int BIGN = (TM * XSTR > TM * HH) ? TM * XSTR : TM * HH;
    __shared__ __align__(16) float S_big[BIGN];   // h1 first, then xs (h1 dead by then)
    float* S_h1 = S_big;
    float* S_xs = S_big;

    const int tid = threadIdx.x;
    const int i0 = blockIdx.x * TM;

    // --- stage 0: params + edge tile + indices ---
    for (int j = tid; j < S_DIM * HH; j += NT) S_w0[j] = w0[j];
    for (int j = tid; j < HH; j += NT) { S_b0v[j] = b0[j]; S_b1v[j] = b1[j]; }
    for (int j = tid; j < HH * HH; j += NT) S_w1[j] = w1[j];
    for (int j = tid; j < TM * S_DIM; j += NT) S_ef[j] = efeat[(size_t)i0 * S_DIM + j];
    for (int j = tid; j < TM; j += NT) { S_src[j] = src[i0 + j]; S_tgt[j] = tgt[i0 + j]; }
    __syncthreads();

    // --- edge MLP: h1 = relu(e@w0+b0) ---
    for (int j = tid; j < TM * HH; j += NT) {
        int i = j / HH, jj = j - i * HH;
        float a = S_b0v[jj];
        #pragma unroll
        for (int s = 0; s < S_DIM; s++) a += S_ef[i * S_DIM + s] * S_w0[s * HH + jj];
        S_h1[j] = fmaxf(a, 0.f);
    }
    __syncthreads();
    // --- h2 = relu(h1@w1+b1) ---
    for (int j = tid; j < TM * HH; j += NT) {
        int i = j / HH, jj = j - i * HH;
        float a = S_b1v[jj];
        #pragma unroll
        for (int h = 0; h < HH; h++) a += S_h1[i * HH + h] * S_w1[h * HH + jj];
        S_h2[j] = fmaxf(a, 0.f);
    }
    __syncthreads();   // h1 dead; xs overlay may now be written

    // --- gather x[src] into padded smem rows ---
    if constexpr (F == 32) {
        for (int j = tid; j < TM * 8; j += NT) {
            int i = j >> 3, q = j & 7;
            float4 v = __ldg((const float4*)(xin + (size_t)S_src[i] * F) + q);
            if (RELU_IN) { v.x = fmaxf(v.x, 0.f); v.y = fmaxf(v.y, 0.f);
                           v.z = fmaxf(v.z, 0.f); v.w = fmaxf(v.w, 0.f); }
            *(float4*)(S_xs + i * XSTR + q * 4) = v;
        }
    } else {
        for (int j = tid; j < TM * F; j += NT) {
            int i = j / F, f = j - i * F;
            float v = __ldg(xin + (size_t)S_src[i] * F + f);
            S_xs[i * XSTR + f] = RELU_IN ? fmaxf(v, 0.f) : v;
        }
    }
    __syncthreads();

    // --- warp-tile GEMM: warp w covers rows [16w,16w+16) x all C cols ---
    const int lane = tid & 31, wid = tid >> 5;
    const int qr = lane >> 2;          // 0..7
    const int ka = (lane & 3) * 2;     // 0,2,4,6
    const int r0 = wid * 16 + qr, r1 = r0 + 8;

    float acc[NNT][4];
    #pragma unroll
    for (int nt = 0; nt < NNT; nt++) {
        acc[nt][0] = 0.f; acc[nt][1] = 0.f; acc[nt][2] = 0.f; acc[nt][3] = 0.f;
    }

    for (int kc = 0; kc < NKC; kc++) {
        // build A hi/lo fragments in registers
        uint32_t ah[4], al[4];
        if constexpr (F == 32) {
            float hs0, hs1;
            if (kc < KMAIN / 16) {
                hs0 = S_h2[r0 * HH + (kc >> 1)];
                hs1 = S_h2[r1 * HH + (kc >> 1)];
            } else { hs0 = 1.f; hs1 = 1.f; }
            const int f0 = (kc & 1) * 16;
            const float2 x00 = *(const float2*)(S_xs + r0 * XSTR + f0 + ka);
            const float2 x02 = *(const float2*)(S_xs + r0 * XSTR + f0 + ka + 8);
            const float2 x10 = *(const float2*)(S_xs + r1 * XSTR + f0 + ka);
            const float2 x12 = *(const float2*)(S_xs + r1 * XSTR + f0 + ka + 8);
            splitpair(ah[0], al[0], hs0 * x00.x, hs0 * x00.y);
            splitpair(ah[1], al[1], hs1 * x10.x, hs1 * x10.y);
            splitpair(ah[2], al[2], hs0 * x02.x, hs0 * x02.y);
            splitpair(ah[3], al[3], hs1 * x12.x, hs1 * x12.y);
        } else {
            float p0[4], p1[4];       // [jj*2+dd] for rows r0, r1
            const int kb = kc * 16 + ka;
            #pragma unroll
            for (int jj = 0; jj < 2; jj++) {
                #pragma unroll
                for (int dd = 0; dd < 2; dd++) {
                    int k = kb + jj * 8 + dd;
                    float v0 = 0.f, v1 = 0.f;
                    if (k < KMAIN) {
                        int h = k / F, f = k - h * F;
                        v0 = S_h2[r0 * HH + h] * S_xs[r0 * XSTR + f];
                        v1 = S_h2[r1 * HH + h] * S_xs[r1 * XSTR + f];
                    } else if (k < KTOT) {
                        int f = k - KMAIN;
                        v0 = S_xs[r0 * XSTR + f];
                        v1 = S_xs[r1 * XSTR + f];
                    }
                    p0[jj * 2 + dd] = v0; p1[jj * 2 + dd] = v1;
                }
            }
            splitpair(ah[0], al[0], p0[0], p0[1]);
            splitpair(ah[1], al[1], p1[0], p1[1]);
            splitpair(ah[2], al[2], p0[2], p0[3]);
            splitpair(ah[3], al[3], p1[2], p1[3]);
        }

        // B fragments straight from global (L1/L2 resident) + 3-term MMA
        #pragma unroll
        for (int nt = 0; nt < NNT; nt++) {
            const size_t bofs = (size_t)(nt * 8 + qr) * KPAD + kc * 16 + ka;
            uint32_t bh0 = *(const uint32_t*)(wtHi + bofs);
            uint32_t bh1 = *(const uint32_t*)(wtHi + bofs + 8);
            uint32_t bl0 = *(const uint32_t*)(wtLo + bofs);
            uint32_t bl1 = *(const uint32_t*)(wtLo + bofs + 8);
            mma_bf16(acc[nt], ah, bh0, bh1);
            mma_bf16(acc[nt], al, bh0, bh1);
            mma_bf16(acc[nt], ah, bl0, bl1);
        }
    }

    // --- scatter-add to agg[tgt] ---
    float* dst0 = agg + (size_t)S_tgt[r0] * C + ka;
    float* dst1 = agg + (size_t)S_tgt[r1] * C + ka;
    #pragma unroll
    for (int nt = 0; nt < NNT; nt++) {
        red2(dst0 + nt * 8, acc[nt][0], acc[nt][1]);
        red2(dst1 + nt * 8, acc[nt][2], acc[nt][3]);
    }
}

// ---------------- node GEMM: out[n,c] = [bias[c]] + relu?(x[n,:]) @ root[:,c] ----------------
template <int F, int C, bool BIAS, bool RELU_IN>
__global__ __launch_bounds__(256) void base2_kernel(
    const float* __restrict__ x, const float* __restrict__ root,
    const float* __restrict__ bias, float* __restrict__ out)
{
    __shared__ float sroot[F * C];
    __shared__ float sb[C];
    const int tid = threadIdx.x;
    for (int j = tid; j < F * C; j += 256) sroot[j] = root[j];
    if (BIAS) for (int j = tid; j < C; j += 256) sb[j] = bias[j];
    __syncthreads();

    constexpr int QC = C / 4;
    int idx = blockIdx.x * 256 + tid;
    int n = idx / QC, q = (idx - n * QC) * 4;
    if (n >= N_NODES) return;

    float4 a = BIAS ? make_float4(sb[q], sb[q + 1], sb[q + 2], sb[q + 3])
                    : make_float4(0.f, 0.f, 0.f, 0.f);
    const float* xr = x + (size_t)n * F;
    #pragma unroll
    for (int f = 0; f < F; f++) {
        float xv = __ldg(xr + f);
        if (RELU_IN) xv = fmaxf(xv, 0.f);
        float4 rv = *(const float4*)&sroot[f * C + q];
        a.x += xv * rv.x; a.y += xv * rv.y; a.z += xv * rv.z; a.w += xv * rv.w;
    }
    *(float4*)(out + (size_t)n * C + q) = a;
}

__global__ void zero_kernel(float* __restrict__ buf, int n)
{
    int i = blockIdx.x * blockDim.x + threadIdx.x;
    if (i < n) buf[i] = 0.f;
}

// GCN weighted SpMM: b3[tgt, :] += w * xw[src, :]
__global__ void gcn_edge_kernel(const float* __restrict__ xw,
                                const int* __restrict__ gs, const int* __restrict__ gt,
                                const float* __restrict__ gw, float* __restrict__ b3)
{
    int idx = blockIdx.x * blockDim.x + threadIdx.x;
    int m = idx >> 3, q = (idx & 7) * 4;
    if (m >= N_EDGES + N_NODES) return;
    float w = __ldg(gw + m);
    float4 v = __ldg((const float4*)(xw + (size_t)__ldg(gs + m) * C3 + q));
    red4(b3 + (size_t)__ldg(gt + m) * C3 + q, w * v.x, w * v.y, w * v.z, w * v.w);
}

// x3 = relu(b3 + gcn_b); out[seg[n], :] += x3[n, :]
__global__ void pool_kernel(const float* __restrict__ b3, const float* __restrict__ gb,
                            const int* __restrict__ seg, float* __restrict__ out)
{
    int idx = blockIdx.x * blockDim.x + threadIdx.x;
    int n = idx >> 3, q = (idx & 7) * 4;
    if (n >= N_NODES) return;
    float4 v = *(const float4*)(b3 + (size_t)n * C3 + q);
    float a = fmaxf(v.x + __ldg(gb + q), 0.f);
    float b = fmaxf(v.y + __ldg(gb + q + 1), 0.f);
    float c = fmaxf(v.z + __ldg(gb + q + 2), 0.f);
    float d = fmaxf(v.w + __ldg(gb + q + 3), 0.f);
    red4(out + (size_t)__ldg(seg + n) * C3 + q, a, b, c, d);
}

// ---------------- launch ----------------
extern "C" void kernel_launch(void* const* d_in, const int* in_sizes, int n_in,
                              void* d_out, int out_size)
{
    (void)in_sizes; (void)n_in; (void)out_size;
    const float* x     = (const float*)d_in[0];
    const float* e     = (const float*)d_in[1];
    const int*   src   = (const int*)d_in[2];
    const int*   tgt   = (const int*)d_in[3];
    const int*   seg   = (const int*)d_in[4];
    const int*   gsrc  = (const int*)d_in[5];
    const int*   gtgt  = (const int*)d_in[6];
    const float* gw    = (const float*)d_in[7];
    const float* e1_w0 = (const float*)d_in[8];
    const float* e1_b0 = (const float*)d_in[9];
    const float* e1_w1 = (const float*)d_in[10];
    const float* e1_b1 = (const float*)d_in[11];
    const float* e1_wk = (const float*)d_in[12];
    const float* e1_bk = (const float*)d_in[13];
    const float* e1_root = (const float*)d_in[14];
    const float* e1_bias = (const float*)d_in[15];
    const float* e2_w0 = (const float*)d_in[16];
    const float* e2_b0 = (const float*)d_in[17];
    const float* e2_w1 = (const float*)d_in[18];
    const float* e2_b1 = (const float*)d_in[19];
    const float* e2_wk = (const float*)d_in[20];
    const float* e2_bk = (const float*)d_in[21];
    const float* e2_root = (const float*)d_in[22];
    const float* e2_bias = (const float*)d_in[23];
    const float* gcn_W = (const float*)d_in[24];
    const float* gcn_b = (const float*)d_in[25];
    float* out = (float*)d_out;

    float *B1, *B2, *XW, *B3;
    __nv_bfloat16 *WT1h, *WT1l, *WT2h, *WT2l;
    cudaGetSymbolAddress((void**)&B1, g_B1);
    cudaGetSymbolAddress((void**)&B2, g_B2);
    cudaGetSymbolAddress((void**)&XW, g_XW);
    cudaGetSymbolAddress((void**)&B3, g_B3);
    cudaGetSymbolAddress((void**)&WT1h, g_WT1_hi);
    cudaGetSymbolAddress((void**)&WT1l, g_WT1_lo);
    cudaGetSymbolAddress((void**)&WT2h, g_WT2_hi);
    cudaGetSymbolAddress((void**)&WT2l, g_WT2_lo);

    // weight pre-transpose + bf16 hi/lo split
    prep_wt_kernel<C1, K1MAIN, K1TOT, K1PAD><<<(C1 * K1PAD + 255) / 256, 256>>>(e1_wk, e1_bk, WT1h, WT1l);
    prep_wt_kernel<C2, K2MAIN, K2TOT, K2PAD><<<(C2 * K2PAD + 255) / 256, 256>>>(e2_wk, e2_bk, WT2h, WT2l);

    // ECC layer 1: B1 = x@root1 + bias1 + messages (relu deferred to readers)
    base2_kernel<F_IN, C1, true, false><<<(N_NODES * (C1 / 4) + 255) / 256, 256>>>(x, e1_root, e1_bias, B1);
    ecc_mma_kernel<F_IN, C1, K1PAD, false><<<N_EDGES / 128, 256>>>(
        x, e, src, tgt, e1_w0, e1_b0, e1_w1, e1_b1, WT1h, WT1l, B1);

    // ECC layer 2 (readers apply relu to B1)
    base2_kernel<C1, C2, true, true><<<(N_NODES * (C2 / 4) + 255) / 256, 256>>>(B1, e2_root, e2_bias, B2);
    ecc_mma_kernel<C1, C2, K2PAD, true><<<N_EDGES / 128, 256>>>(
        B1, e, src, tgt, e2_w0, e2_b0, e2_w1, e2_b1, WT2h, WT2l, B2);

    // GCN: xw = relu(B2) @ W ; B3 = scatter(gcn_w * xw[gcn_src] -> gcn_tgt)
    base2_kernel<C2, C3, false, true><<<(N_NODES * (C3 / 4) + 255) / 256, 256>>>(B2, gcn_W, nullptr, XW);
    zero_kernel<<<(N_NODES * C3 + 255) / 256, 256>>>(B3, N_NODES * C3);
    gcn_edge_kernel<<<((N_EDGES + N_NODES) * 8 + 255) / 256, 256>>>(XW, gsrc, gtgt, gw, B3);

    // relu(+bias) and global sum pool
    zero_kernel<<<(G_NUM * C3 + 255) / 256, 256>>>(out, G_NUM * C3);
    pool_kernel<<<(N_NODES * 8 + 255) / 256, 256>>>(B3, gcn_b, seg, out);
}

// round 9
// speedup vs baseline: 4.0726x; 2.2272x over previous
#include <cuda_runtime.h>
#include <cuda_bf16.h>
#include <cstdint>

#define N_NODES 16384
#define N_EDGES 131072
#define F_IN 6
#define S_DIM 4
#define G_NUM 256
#define HH 30
#define C1 32
#define C2 64
#define C3 32

#define K1MAIN (HH * F_IN)      // 180
#define K1TOT  (K1MAIN + F_IN)  // 186
#define K1PAD  192
#define NKC1   (K1PAD / 16)     // 12
#define K2MAIN (HH * C1)        // 960
#define K2TOT  (K2MAIN + C1)    // 992
#define K2PAD  992
#define NKC2   (K2PAD / 16)     // 62

// ---------------- scratch (no cudaMalloc allowed) ----------------
__device__ float g_B1[N_NODES * C1];
__device__ float g_B2[N_NODES * C2];
__device__ float g_XW[N_NODES * C3];
__device__ float g_B3[N_NODES * C3];
__device__ uint4 g_WTP1[NKC1 * C1 * 4];   // fragment-packed {bh0,bh1,bl0,bl1}
__device__ uint4 g_WTP2[NKC2 * C2 * 4];

// ---------------- helpers ----------------
__device__ __forceinline__ void red4(float* p, float a, float b, float c, float d) {
    asm volatile("red.global.add.v4.f32 [%0], {%1, %2, %3, %4};"
                 :: "l"(p), "f"(a), "f"(b), "f"(c), "f"(d) : "memory");
}
__device__ __forceinline__ void red2(float* p, float a, float b) {
    asm volatile("red.global.add.v2.f32 [%0], {%1, %2};"
                 :: "l"(p), "f"(a), "f"(b) : "memory");
}
// pack (pA -> low half, pB -> high half) as bf16x2 hi, and residual lo
__device__ __forceinline__ void splitpair(uint32_t& h, uint32_t& l, float pA, float pB) {
    asm("cvt.rn.bf16x2.f32 %0, %1, %2;" : "=r"(h) : "f"(pB), "f"(pA));
    float rA = pA - __uint_as_float(h << 16);
    float rB = pB - __uint_as_float(h & 0xffff0000u);
    asm("cvt.rn.bf16x2.f32 %0, %1, %2;" : "=r"(l) : "f"(rB), "f"(rA));
}
__device__ __forceinline__ void mma_bf16(float* c, const uint32_t* a, uint32_t b0, uint32_t b1) {
    asm volatile("mma.sync.aligned.m16n8k16.row.col.f32.bf16.bf16.f32 "
                 "{%0,%1,%2,%3}, {%4,%5,%6,%7}, {%8,%9}, {%0,%1,%2,%3};"
                 : "+f"(c[0]), "+f"(c[1]), "+f"(c[2]), "+f"(c[3])
                 : "r"(a[0]), "r"(a[1]), "r"(a[2]), "r"(a[3]), "r"(b0), "r"(b1));
}

// ---------------- weight prep: transpose + bf16 hi/lo split, fragment-packed ----------------
// out[(kc*C + c)*4 + q] = {bh0, bh1, bl0, bl1} for col c, k-pair base kc*16 + q*2 (and +8)
template <int C, int KMAIN, int KTOT, int NKC>
__global__ void prep_wt_kernel(const float* __restrict__ wk, const float* __restrict__ bk,
                               uint4* __restrict__ out)
{
    int idx = blockIdx.x * 256 + threadIdx.x;
    if (idx >= NKC * C * 4) return;
    int kc = idx >> 8 ? idx / (C * 4) : 0;  // computed properly below
    kc = idx / (C * 4);
    int rem = idx - kc * (C * 4);
    int c = rem >> 2, q = rem & 3;
    int k0 = kc * 16 + q * 2;
    float v[4];
    #pragma unroll
    for (int t = 0; t < 4; t++) {
        int k = k0 + (t >> 1) * 8 + (t & 1);
        float x = 0.f;
        if (k < KMAIN)      x = __ldg(wk + (size_t)k * C + c);
        else if (k < KTOT)  x = __ldg(bk + (size_t)(k - KMAIN) * C + c);
        v[t] = x;
    }
    uint4 o;
    splitpair(o.x, o.z, v[0], v[1]);
    splitpair(o.y, o.w, v[2], v[3]);
    out[idx] = o;
}

// ---------------- smem struct (dynamic) ----------------
struct ESm {
    float w0p[S_DIM * 32];
    float b0p[32];
    float b1p[32];
    float w1p[HH * 32];
    float ef[256 * S_DIM];
    int   srcs[256];
    int   tgts[256];
    float h2[256 * 36];
    float big[256 * 36];   // h1 (stride 36) first, then xs (stride XSTR)
};

// ---------------- ECC layer: fused edge-MLP + bf16 3-MMA GEMM + scatter ----------------
template <int F, int C, int NKC, bool RELU_IN>
__global__ __launch_bounds__(256, 2) void ecc_mma_kernel(
    const float* __restrict__ xin, const float* __restrict__ efeat,
    const int* __restrict__ src, const int* __restrict__ tgt,
    const float* __restrict__ w0, const float* __restrict__ b0,
    const float* __restrict__ w1, const float* __restrict__ b1,
    const uint4* __restrict__ wtp,
    float* __restrict__ agg)
{
    constexpr int NT = 256, TM = 256;
    constexpr int XSTR = (F == 32) ? 36 : 8;
    constexpr int NNT = C / 8;
    constexpr int KMAIN = HH * F;
    constexpr int KTOT = KMAIN + F;

    extern __shared__ __align__(16) char smraw[];
    ESm& S = *reinterpret_cast<ESm*>(smraw);
    float* S_h1 = S.big;   // stride 36
    float* S_xs = S.big;   // stride XSTR (after h2 done)

    const int tid = threadIdx.x;
    const int i0 = blockIdx.x * TM;

    // --- stage 0: params (padded) + edge tile + indices ---
    for (int j = tid; j < S_DIM * 32; j += NT) {
        int s = j >> 5, jj = j & 31;
        S.w0p[j] = (jj < HH) ? w0[s * HH + jj] : 0.f;
    }
    for (int j = tid; j < 32; j += NT) {
        S.b0p[j] = (j < HH) ? b0[j] : 0.f;
        S.b1p[j] = (j < HH) ? b1[j] : 0.f;
    }
    for (int j = tid; j < HH * 32; j += NT) {
        int h = j >> 5, jj = j & 31;
        S.w1p[j] = (jj < HH) ? w1[h * HH + jj] : 0.f;
    }
    for (int j = tid; j < TM; j += NT) {
        *(float4*)&S.ef[j * 4] = __ldg((const float4*)efeat + i0 + j);
        S.srcs[j] = src[i0 + j];
        S.tgts[j] = tgt[i0 + j];
    }
    __syncthreads();

    // --- h1 = relu(e@w0+b0): 4 rows x 4 cols per thread-item ---
    #pragma unroll
    for (int t = 0; t < 2; t++) {
        int it = tid + t * NT;
        int ib = it >> 3, jg = it & 7;
        float4 bb = *(const float4*)&S.b0p[jg * 4];
        float4 a[4] = {bb, bb, bb, bb};
        #pragma unroll
        for (int s = 0; s < S_DIM; s++) {
            float4 w = *(const float4*)&S.w0p[s * 32 + jg * 4];
            #pragma unroll
            for (int r = 0; r < 4; r++) {
                float e = S.ef[(ib * 4 + r) * S_DIM + s];
                a[r].x += e * w.x; a[r].y += e * w.y; a[r].z += e * w.z; a[r].w += e * w.w;
            }
        }
        #pragma unroll
        for (int r = 0; r < 4; r++) {
            float4 h = make_float4(fmaxf(a[r].x, 0.f), fmaxf(a[r].y, 0.f),
                                   fmaxf(a[r].z, 0.f), fmaxf(a[r].w, 0.f));
            *(float4*)&S_h1[(ib * 4 + r) * 36 + jg * 4] = h;
        }
    }
    __syncthreads();

    // --- h2 = relu(h1@w1+b1) ---
    #pragma unroll
    for (int t = 0; t < 2; t++) {
        int it = tid + t * NT;
        int ib = it >> 3, jg = it & 7;
        float4 bb = *(const float4*)&S.b1p[jg * 4];
        float4 a[4] = {bb, bb, bb, bb};
        for (int h = 0; h < HH; h++) {
            float4 w = *(const float4*)&S.w1p[h * 32 + jg * 4];
            #pragma unroll
            for (int r = 0; r < 4; r++) {
                float hv = S_h1[(ib * 4 + r) * 36 + h];
                a[r].x += hv * w.x; a[r].y += hv * w.y; a[r].z += hv * w.z; a[r].w += hv * w.w;
            }
        }
        #pragma unroll
        for (int r = 0; r < 4; r++) {
            float4 h = make_float4(fmaxf(a[r].x, 0.f), fmaxf(a[r].y, 0.f),
                                   fmaxf(a[r].z, 0.f), fmaxf(a[r].w, 0.f));
            *(float4*)&S.h2[(ib * 4 + r) * 36 + jg * 4] = h;
        }
    }
    __syncthreads();   // h1 dead; big[] may be overwritten with xs

    // --- gather x[src] ---
    if constexpr (F == 32) {
        for (int j = tid; j < TM * 8; j += NT) {
            int i = j >> 3, q = j & 7;
            float4 v = __ldg((const float4*)(xin + (size_t)S.srcs[i] * F) + q);
            if (RELU_IN) { v.x = fmaxf(v.x, 0.f); v.y = fmaxf(v.y, 0.f);
                           v.z = fmaxf(v.z, 0.f); v.w = fmaxf(v.w, 0.f); }
            *(float4*)(S_xs + i * XSTR + q * 4) = v;
        }
    } else {
        for (int j = tid; j < TM * F; j += NT) {
            int i = j / F, f = j - i * F;
            float v = __ldg(xin + (size_t)S.srcs[i] * F + f);
            S_xs[i * XSTR + f] = RELU_IN ? fmaxf(v, 0.f) : v;
        }
    }
    __syncthreads();

    // --- warp-tile GEMM: warp covers rows [32w, 32w+32) x all C (2 m16 tiles) ---
    const int lane = tid & 31, wid = tid >> 5;
    const int qr = lane >> 2;
    const int kq = lane & 3;
    const int ka = kq * 2;
    const int rr[4] = { wid * 32 + qr, wid * 32 + qr + 8,
                        wid * 32 + qr + 16, wid * 32 + qr + 24 };

    float acc[2][NNT][4];
    #pragma unroll
    for (int m = 0; m < 2; m++)
        #pragma unroll
        for (int nt = 0; nt < NNT; nt++) {
            acc[m][nt][0] = 0.f; acc[m][nt][1] = 0.f;
            acc[m][nt][2] = 0.f; acc[m][nt][3] = 0.f;
        }

    for (int kc = 0; kc < NKC; kc++) {
        uint32_t ah[2][4], al[2][4];
        if constexpr (F == 32) {
            float hs[4];
            if (kc < KMAIN / 16) {
                #pragma unroll
                for (int m = 0; m < 4; m++) hs[m] = S.h2[rr[m] * 36 + (kc >> 1)];
            } else {
                #pragma unroll
                for (int m = 0; m < 4; m++) hs[m] = 1.f;
            }
            const int f0 = (kc & 1) * 16;
            #pragma unroll
            for (int m = 0; m < 2; m++) {
                float2 xa0 = *(const float2*)(S_xs + rr[2 * m] * XSTR + f0 + ka);
                float2 xa8 = *(const float2*)(S_xs + rr[2 * m] * XSTR + f0 + ka + 8);
                float2 xb0 = *(const float2*)(S_xs + rr[2 * m + 1] * XSTR + f0 + ka);
                float2 xb8 = *(const float2*)(S_xs + rr[2 * m + 1] * XSTR + f0 + ka + 8);
                splitpair(ah[m][0], al[m][0], hs[2 * m] * xa0.x, hs[2 * m] * xa0.y);
                splitpair(ah[m][1], al[m][1], hs[2 * m + 1] * xb0.x, hs[2 * m + 1] * xb0.y);
                splitpair(ah[m][2], al[m][2], hs[2 * m] * xa8.x, hs[2 * m] * xa8.y);
                splitpair(ah[m][3], al[m][3], hs[2 * m + 1] * xb8.x, hs[2 * m + 1] * xb8.y);
            }
        } else {
            float p[4][4];   // [row][jj*2+dd]
            const int kb = kc * 16 + ka;
            #pragma unroll
            for (int jj = 0; jj < 2; jj++) {
                #pragma unroll
                for (int dd = 0; dd < 2; dd++) {
                    int k = kb + jj * 8 + dd;
                    #pragma unroll
                    for (int m = 0; m < 4; m++) {
                        float v = 0.f;
                        if (k < KMAIN) {
                            int h = k / F, f = k - h * F;
                            v = S.h2[rr[m] * 36 + h] * S_xs[rr[m] * XSTR + f];
                        } else if (k < KTOT) {
                            v = S_xs[rr[m] * XSTR + (k - KMAIN)];
                        }
                        p[m][jj * 2 + dd] = v;
                    }
                }
            }
            #pragma unroll
            for (int m = 0; m < 2; m++) {
                splitpair(ah[m][0], al[m][0], p[2 * m][0], p[2 * m][1]);
                splitpair(ah[m][1], al[m][1], p[2 * m + 1][0], p[2 * m + 1][1]);
                splitpair(ah[m][2], al[m][2], p[2 * m][2], p[2 * m][3]);
                splitpair(ah[m][3], al[m][3], p[2 * m + 1][2], p[2 * m + 1][3]);
            }
        }

        #pragma unroll
        for (int nt = 0; nt < NNT; nt++) {
            uint4 bf = __ldg(&wtp[(size_t)(kc * C + nt * 8 + qr) * 4 + kq]);
            #pragma unroll
            for (int m = 0; m < 2; m++) {
                mma_bf16(acc[m][nt], ah[m], bf.x, bf.y);
                mma_bf16(acc[m][nt], al[m], bf.x, bf.y);
                mma_bf16(acc[m][nt], ah[m], bf.z, bf.w);
            }
        }
    }

    // --- scatter-add to agg[tgt] ---
    #pragma unroll
    for (int m = 0; m < 2; m++) {
        float* d0 = agg + (size_t)S.tgts[rr[2 * m]] * C + ka;
        float* d1 = agg + (size_t)S.tgts[rr[2 * m + 1]] * C + ka;
        #pragma unroll
        for (int nt = 0; nt < NNT; nt++) {
            red2(d0 + nt * 8, acc[m][nt][0], acc[m][nt][1]);
            red2(d1 + nt * 8, acc[m][nt][2], acc[m][nt][3]);
        }
    }
}

// ---------------- node GEMM: out[n,c] = [bias[c]] + relu?(x[n,:]) @ root[:,c] ----------------
template <int F, int C, bool BIAS, bool RELU_IN>
__global__ __launch_bounds__(256) void base2_kernel(
    const float* __restrict__ x, const float* __restrict__ root,
    const float* __restrict__ bias, float* __restrict__ out)
{
    __shared__ float sroot[F * C];
    __shared__ float sb[C];
    const int tid = threadIdx.x;
    for (int j = tid; j < F * C; j += 256) sroot[j] = root[j];
    if (BIAS) for (int j = tid; j < C; j += 256) sb[j] = bias[j];
    __syncthreads();

    constexpr int QC = C / 4;
    int idx = blockIdx.x * 256 + tid;
    int n = idx / QC, q = (idx - n * QC) * 4;
    if (n >= N_NODES) return;

    float4 a = BIAS ? make_float4(sb[q], sb[q + 1], sb[q + 2], sb[q + 3])
                    : make_float4(0.f, 0.f, 0.f, 0.f);
    const float* xr = x + (size_t)n * F;
    #pragma unroll
    for (int f = 0; f < F; f++) {
        float xv = __ldg(xr + f);
        if (RELU_IN) xv = fmaxf(xv, 0.f);
        float4 rv = *(const float4*)&sroot[f * C + q];
        a.x += xv * rv.x; a.y += xv * rv.y; a.z += xv * rv.z; a.w += xv * rv.w;
    }
    *(float4*)(out + (size_t)n * C + q) = a;
}

__global__ void zero_kernel(float* __restrict__ buf, int n)
{
    int i = blockIdx.x * blockDim.x + threadIdx.x;
    if (i < n) buf[i] = 0.f;
}

__global__ void gcn_edge_kernel(const float* __restrict__ xw,
                                const int* __restrict__ gs, const int* __restrict__ gt,
                                const float* __restrict__ gw, float* __restrict__ b3)
{
    int idx = blockIdx.x * blockDim.x + threadIdx.x;
    int m = idx >> 3, q = (idx & 7) * 4;
    if (m >= N_EDGES + N_NODES) return;
    float w = __ldg(gw + m);
    float4 v = __ldg((const float4*)(xw + (size_t)__ldg(gs + m) * C3 + q));
    red4(b3 + (size_t)__ldg(gt + m) * C3 + q, w * v.x, w * v.y, w * v.z, w * v.w);
}

__global__ void pool_kernel(const float* __restrict__ b3, const float* __restrict__ gb,
                            const int* __restrict__ seg, float* __restrict__ out)
{
    int idx = blockIdx.x * blockDim.x + threadIdx.x;
    int n = idx >> 3, q = (idx & 7) * 4;
    if (n >= N_NODES) return;
    float4 v = *(const float4*)(b3 + (size_t)n * C3 + q);
    float a = fmaxf(v.x + __ldg(gb + q), 0.f);
    float b = fmaxf(v.y + __ldg(gb + q + 1), 0.f);
    float c = fmaxf(v.z + __ldg(gb + q + 2), 0.f);
    float d = fmaxf(v.w + __ldg(gb + q + 3), 0.f);
    red4(out + (size_t)__ldg(seg + n) * C3 + q, a, b, c, d);
}

// ---------------- launch ----------------
extern "C" void kernel_launch(void* const* d_in, const int* in_sizes, int n_in,
                              void* d_out, int out_size)
{
    (void)in_sizes; (void)n_in; (void)out_size;
    const float* x     = (const float*)d_in[0];
    const float* e     = (const float*)d_in[1];
    const int*   src   = (const int*)d_in[2];
    const int*   tgt   = (const int*)d_in[3];
    const int*   seg   = (const int*)d_in[4];
    const int*   gsrc  = (const int*)d_in[5];
    const int*   gtgt  = (const int*)d_in[6];
    const float* gw    = (const float*)d_in[7];
    const float* e1_w0 = (const float*)d_in[8];
    const float* e1_b0 = (const float*)d_in[9];
    const float* e1_w1 = (const float*)d_in[10];
    const float* e1_b1 = (const float*)d_in[11];
    const float* e1_wk = (const float*)d_in[12];
    const float* e1_bk = (const float*)d_in[13];
    const float* e1_root = (const float*)d_in[14];
    const float* e1_bias = (const float*)d_in[15];
    const float* e2_w0 = (const float*)d_in[16];
    const float* e2_b0 = (const float*)d_in[17];
    const float* e2_w1 = (const float*)d_in[18];
    const float* e2_b1 = (const float*)d_in[19];
    const float* e2_wk = (const float*)d_in[20];
    const float* e2_bk = (const float*)d_in[21];
    const float* e2_root = (const float*)d_in[22];
    const float* e2_bias = (const float*)d_in[23];
    const float* gcn_W = (const float*)d_in[24];
    const float* gcn_b = (const float*)d_in[25];
    float* out = (float*)d_out;

    float *B1, *B2, *XW, *B3;
    uint4 *WTP1, *WTP2;
    cudaGetSymbolAddress((void**)&B1, g_B1);
    cudaGetSymbolAddress((void**)&B2, g_B2);
    cudaGetSymbolAddress((void**)&XW, g_XW);
    cudaGetSymbolAddress((void**)&B3, g_B3);
    cudaGetSymbolAddress((void**)&WTP1, g_WTP1);
    cudaGetSymbolAddress((void**)&WTP2, g_WTP2);

    const int smem = (int)sizeof(ESm);
    cudaFuncSetAttribute((const void*)ecc_mma_kernel<F_IN, C1, NKC1, false>,
                         cudaFuncAttributeMaxDynamicSharedMemorySize, smem);
    cudaFuncSetAttribute((const void*)ecc_mma_kernel<C1, C2, NKC2, true>,
                         cudaFuncAttributeMaxDynamicSharedMemorySize, smem);

    // weight prep (fragment-packed bf16 hi/lo)
    prep_wt_kernel<C1, K1MAIN, K1TOT, NKC1><<<(NKC1 * C1 * 4 + 255) / 256, 256>>>(e1_wk, e1_bk, WTP1);
    prep_wt_kernel<C2, K2MAIN, K2TOT, NKC2><<<(NKC2 * C2 * 4 + 255) / 256, 256>>>(e2_wk, e2_bk, WTP2);

    // ECC layer 1: B1 = x@root1 + bias1 + messages (relu deferred to readers)
    base2_kernel<F_IN, C1, true, false><<<(N_NODES * (C1 / 4) + 255) / 256, 256>>>(x, e1_root, e1_bias, B1);
    ecc_mma_kernel<F_IN, C1, NKC1, false><<<N_EDGES / 256, 256, smem>>>(
        x, e, src, tgt, e1_w0, e1_b0, e1_w1, e1_b1, WTP1, B1);

    // ECC layer 2 (readers apply relu to B1)
    base2_kernel<C1, C2, true, true><<<(N_NODES * (C2 / 4) + 255) / 256, 256>>>(B1, e2_root, e2_bias, B2);
    ecc_mma_kernel<C1, C2, NKC2, true><<<N_EDGES / 256, 256, smem>>>(
        B1, e, src, tgt, e2_w0, e2_b0, e2_w1, e2_b1, WTP2, B2);

    // GCN: xw = relu(B2) @ W ; B3 = scatter(gcn_w * xw[gcn_src] -> gcn_tgt)
    base2_kernel<C2, C3, false, true><<<(N_NODES * (C3 / 4) + 255) / 256, 256>>>(B2, gcn_W, nullptr, XW);
    zero_kernel<<<(N_NODES * C3 + 255) / 256, 256>>>(B3, N_NODES * C3);
    gcn_edge_kernel<<<((N_EDGES + N_NODES) * 8 + 255) / 256, 256>>>(XW, gsrc, gtgt, gw, B3);

    // relu(+bias) and global sum pool
    zero_kernel<<<(G_NUM * C3 + 255) / 256, 256>>>(out, G_NUM * C3);
    pool_kernel<<<(N_NODES * 8 + 255) / 256, 256>>>(B3, gcn_b, seg, out);
}